// round 6
// baseline (speedup 1.0000x reference)
#include <cuda_runtime.h>

static constexpr int Tn = 512;
static constexpr int Bn = 512;
static constexpr long BTn = (long)Bn * Tn;

// Scratch (device globals; allocation-free kernel_launch)
__device__ float g_xg[(size_t)512 * 512 * 288];   // max 4H = 288
__device__ float g_seqA[(size_t)512 * 512 * 64];  // e1 out / d1 out
__device__ float g_seqB[(size_t)512 * 512 * 32];  // e2 out

__device__ __forceinline__ float fsig(float x) {
    return __fdividef(1.0f, 1.0f + __expf(-x));
}
__device__ __forceinline__ float ftanh(float x) {
    return 1.0f - __fdividef(2.0f, __expf(2.0f * x) + 1.0f);
}

// ---- packed f32x2 helpers (Blackwell) ----
__device__ __forceinline__ unsigned long long pk2(float lo, float hi) {
    unsigned long long r;
    asm("mov.b64 %0, {%1, %2};" : "=l"(r) : "f"(lo), "f"(hi));
    return r;
}
__device__ __forceinline__ void upk2(unsigned long long v, float& lo, float& hi) {
    asm("mov.b64 {%0, %1}, %2;" : "=f"(lo), "=f"(hi) : "l"(v));
}
__device__ __forceinline__ unsigned long long ffma2(
    unsigned long long a, unsigned long long b, unsigned long long c) {
    unsigned long long d;
    asm("fma.rn.f32x2 %0, %1, %2, %3;" : "=l"(d) : "l"(a), "l"(b), "l"(c));
    return d;
}

// ---------------------------------------------------------------------------
// Input-projection GEMM (round-2 structure: one gate row per thread, block=G).
// NEW: two SMEM rows per iteration -> 4 independent accumulator chains that
// reuse the same weight registers; chain latency fully hidden by issue.
// ---------------------------------------------------------------------------
template <int IN, int G>
__global__ void __launch_bounds__(G, 2) gemm_xg_kernel(
    const float* __restrict__ in, const float* __restrict__ Wih,
    const float* __restrict__ bih, const float* __restrict__ bhh,
    float* __restrict__ xg)
{
    constexpr int ROWS = 128;
    __shared__ __align__(16) float sIn[ROWS * IN];

    const int g = threadIdx.x;
    const size_t row0 = (size_t)blockIdx.x * ROWS;

    {
        const float4* src = (const float4*)(in + row0 * IN);
        float4* dst = (float4*)sIn;
        constexpr int NV = ROWS * IN / 4;
        for (int i = g; i < NV; i += G) dst[i] = src[i];
    }

    unsigned long long w2[IN / 2];
    {
        const unsigned long long* wp = (const unsigned long long*)(Wih + (size_t)g * IN);
#pragma unroll
        for (int i = 0; i < IN / 2; i++) w2[i] = wp[i];
    }
    const float bias = bih[g] + bhh[g];

    __syncthreads();

    float* outp = xg + row0 * G + g;
#pragma unroll 1
    for (int r = 0; r < ROWS; r += 2) {
        unsigned long long aA = pk2(bias, 0.0f);
        unsigned long long aB = pk2(0.0f, 0.0f);
        unsigned long long bA = pk2(bias, 0.0f);
        unsigned long long bB = pk2(0.0f, 0.0f);
        const ulonglong2* rp0 = (const ulonglong2*)(sIn + r * IN);
        const ulonglong2* rp1 = (const ulonglong2*)(sIn + (r + 1) * IN);
#pragma unroll
        for (int i = 0; i < IN / 4; i++) {
            ulonglong2 v0 = rp0[i];
            ulonglong2 v1 = rp1[i];
            aA = ffma2(w2[2 * i + 0], v0.x, aA);
            aB = ffma2(w2[2 * i + 1], v0.y, aB);
            bA = ffma2(w2[2 * i + 0], v1.x, bA);
            bB = ffma2(w2[2 * i + 1], v1.y, bB);
        }
        float x0, x1, y0, y1;
        upk2(aA, x0, x1);
        upk2(aB, y0, y1);
        outp[(size_t)r * G] = (x0 + x1) + (y0 + y1);
        upk2(bA, x0, x1);
        upk2(bB, y0, y1);
        outp[(size_t)(r + 1) * G] = (x0 + x1) + (y0 + y1);
    }
}

// ---------------------------------------------------------------------------
// Recurrent scan (round-2 structure: block = 4H threads, R batch rows per
// block, 2 barriers/step, xg prefetch). NEW: per-row accumulator split into
// two chains (accA/accB) halving the serial ffma2 depth.
// ---------------------------------------------------------------------------
template <int H, int R, int MINB>
__global__ void __launch_bounds__(4 * H, MINB) lstm_rec_kernel(
    const float* __restrict__ xg, const float* __restrict__ Whh,
    float* __restrict__ hout)
{
    constexpr int G4 = 4 * H;
    __shared__ __align__(16) float h_sm[R * H];
    __shared__ float g_sm[R * G4];

    const int j = threadIdx.x;
    const int b0 = blockIdx.x * R;
    const int gate = j / H;

    unsigned long long w2[H / 2];
    {
        const unsigned long long* wp = (const unsigned long long*)(Whh + (size_t)j * H);
#pragma unroll
        for (int k = 0; k < H / 2; k++) w2[k] = wp[k];
    }

    for (int i = j; i < R * H; i += G4) h_sm[i] = 0.0f;
    float c = 0.0f;

    const float* xgp = xg + (size_t)b0 * Tn * G4 + j;
    float* hp = hout + (size_t)b0 * Tn * H;

    const int cr = j / H;  // cell-update mapping (first R*H threads)
    const int cm = j % H;

    float xn[R];
#pragma unroll
    for (int r = 0; r < R; r++) xn[r] = xgp[(size_t)r * Tn * G4];

    __syncthreads();

    for (int t = 0; t < Tn; t++) {
        unsigned long long accA[R], accB[R];
#pragma unroll
        for (int r = 0; r < R; r++) {
            accA[r] = pk2(xn[r], 0.0f);
            accB[r] = pk2(0.0f, 0.0f);
        }

        if (t + 1 < Tn) {
#pragma unroll
            for (int r = 0; r < R; r++)
                xn[r] = xgp[((size_t)r * Tn + t + 1) * G4];
        }

#pragma unroll
        for (int k = 0; k < H / 4; k++) {
#pragma unroll
            for (int r = 0; r < R; r++) {
                ulonglong2 hv = ((const ulonglong2*)&h_sm[r * H])[k];
                accA[r] = ffma2(w2[2 * k + 0], hv.x, accA[r]);
                accB[r] = ffma2(w2[2 * k + 1], hv.y, accB[r]);
            }
        }

#pragma unroll
        for (int r = 0; r < R; r++) {
            float l0, h0, l1, h1;
            upk2(accA[r], l0, h0);
            upk2(accB[r], l1, h1);
            float a = (l0 + h0) + (l1 + h1);
            a = (gate == 2) ? ftanh(a) : fsig(a);
            g_sm[r * G4 + j] = a;
        }
        __syncthreads();

        if (j < R * H) {
            const float iv = g_sm[cr * G4 + 0 * H + cm];
            const float fv = g_sm[cr * G4 + 1 * H + cm];
            const float gv = g_sm[cr * G4 + 2 * H + cm];
            const float ov = g_sm[cr * G4 + 3 * H + cm];
            c = fv * c + iv * gv;
            const float h = ov * ftanh(c);
            h_sm[cr * H + cm] = h;
            hp[((size_t)cr * Tn + t) * H + cm] = h;
        }
        __syncthreads();
    }
}

// ---------------------------------------------------------------------------
extern "C" void kernel_launch(void* const* d_in, const int* in_sizes, int n_in,
                              void* d_out, int out_size)
{
    (void)in_sizes; (void)n_in; (void)out_size;

    const float* x    = (const float*)d_in[0];
    const float* e1W  = (const float*)d_in[1];
    const float* e1U  = (const float*)d_in[2];
    const float* e1bi = (const float*)d_in[3];
    const float* e1bh = (const float*)d_in[4];
    const float* e2W  = (const float*)d_in[5];
    const float* e2U  = (const float*)d_in[6];
    const float* e2bi = (const float*)d_in[7];
    const float* e2bh = (const float*)d_in[8];
    const float* d1W  = (const float*)d_in[9];
    const float* d1U  = (const float*)d_in[10];
    const float* d1bi = (const float*)d_in[11];
    const float* d1bh = (const float*)d_in[12];
    const float* d2W  = (const float*)d_in[13];
    const float* d2U  = (const float*)d_in[14];
    const float* d2bi = (const float*)d_in[15];
    const float* d2bh = (const float*)d_in[16];
    float* out = (float*)d_out;

    float *xg = nullptr, *sa = nullptr, *sb = nullptr;
    cudaGetSymbolAddress((void**)&xg, g_xg);
    cudaGetSymbolAddress((void**)&sa, g_seqA);
    cudaGetSymbolAddress((void**)&sb, g_seqB);

    const int gemmGrid = (int)(BTn / 128);  // 2048

    // e1: 72 -> 64
    gemm_xg_kernel<72, 256><<<gemmGrid, 256>>>(x, e1W, e1bi, e1bh, xg);
    lstm_rec_kernel<64, 2, 2><<<Bn / 2, 256>>>(xg, e1U, sa);
    // e2: 64 -> 32
    gemm_xg_kernel<64, 128><<<gemmGrid, 128>>>(sa, e2W, e2bi, e2bh, xg);
    lstm_rec_kernel<32, 1, 4><<<Bn, 128>>>(xg, e2U, sb);
    // d1: 32 -> 64
    gemm_xg_kernel<32, 256><<<gemmGrid, 256>>>(sb, d1W, d1bi, d1bh, xg);
    lstm_rec_kernel<64, 2, 2><<<Bn / 2, 256>>>(xg, d1U, sa);
    // d2: 64 -> 72
    gemm_xg_kernel<64, 288><<<gemmGrid, 288>>>(sa, d2W, d2bi, d2bh, xg);
    lstm_rec_kernel<72, 2, 2><<<Bn / 2, 288>>>(xg, d2U, out);
}

// round 7
// speedup vs baseline: 1.0070x; 1.0070x over previous
#include <cuda_runtime.h>

static constexpr int Tn = 512;
static constexpr int Bn = 512;
static constexpr long BTn = (long)Bn * Tn;

// Scratch (device globals; allocation-free kernel_launch)
__device__ float g_xg[(size_t)512 * 512 * 288];   // max 4H = 288
__device__ float g_seqA[(size_t)512 * 512 * 64];  // e1 out / d1 out
__device__ float g_seqB[(size_t)512 * 512 * 32];  // e2 out

__device__ __forceinline__ float fsig(float x) {
    return __fdividef(1.0f, 1.0f + __expf(-x));
}
__device__ __forceinline__ float ftanh(float x) {
    return 1.0f - __fdividef(2.0f, __expf(2.0f * x) + 1.0f);
}

// ---- packed f32x2 helpers (Blackwell) ----
__device__ __forceinline__ unsigned long long pk2(float lo, float hi) {
    unsigned long long r;
    asm("mov.b64 %0, {%1, %2};" : "=l"(r) : "f"(lo), "f"(hi));
    return r;
}
__device__ __forceinline__ void upk2(unsigned long long v, float& lo, float& hi) {
    asm("mov.b64 {%0, %1}, %2;" : "=f"(lo), "=f"(hi) : "l"(v));
}
__device__ __forceinline__ unsigned long long ffma2(
    unsigned long long a, unsigned long long b, unsigned long long c) {
    unsigned long long d;
    asm("fma.rn.f32x2 %0, %1, %2, %3;" : "=l"(d) : "l"(a), "l"(b), "l"(c));
    return d;
}

// ---------------------------------------------------------------------------
// Input-projection GEMM (round-2 structure: one gate row per thread, block=G).
// NEW: two SMEM rows per iteration -> 4 independent accumulator chains that
// reuse the same weight registers; chain latency fully hidden by issue.
// ---------------------------------------------------------------------------
template <int IN, int G>
__global__ void __launch_bounds__(G, 2) gemm_xg_kernel(
    const float* __restrict__ in, const float* __restrict__ Wih,
    const float* __restrict__ bih, const float* __restrict__ bhh,
    float* __restrict__ xg)
{
    constexpr int ROWS = 128;
    __shared__ __align__(16) float sIn[ROWS * IN];

    const int g = threadIdx.x;
    const size_t row0 = (size_t)blockIdx.x * ROWS;

    {
        const float4* src = (const float4*)(in + row0 * IN);
        float4* dst = (float4*)sIn;
        constexpr int NV = ROWS * IN / 4;
        for (int i = g; i < NV; i += G) dst[i] = src[i];
    }

    unsigned long long w2[IN / 2];
    {
        const unsigned long long* wp = (const unsigned long long*)(Wih + (size_t)g * IN);
#pragma unroll
        for (int i = 0; i < IN / 2; i++) w2[i] = wp[i];
    }
    const float bias = bih[g] + bhh[g];

    __syncthreads();

    float* outp = xg + row0 * G + g;
#pragma unroll 1
    for (int r = 0; r < ROWS; r += 2) {
        unsigned long long aA = pk2(bias, 0.0f);
        unsigned long long aB = pk2(0.0f, 0.0f);
        unsigned long long bA = pk2(bias, 0.0f);
        unsigned long long bB = pk2(0.0f, 0.0f);
        const ulonglong2* rp0 = (const ulonglong2*)(sIn + r * IN);
        const ulonglong2* rp1 = (const ulonglong2*)(sIn + (r + 1) * IN);
#pragma unroll
        for (int i = 0; i < IN / 4; i++) {
            ulonglong2 v0 = rp0[i];
            ulonglong2 v1 = rp1[i];
            aA = ffma2(w2[2 * i + 0], v0.x, aA);
            aB = ffma2(w2[2 * i + 1], v0.y, aB);
            bA = ffma2(w2[2 * i + 0], v1.x, bA);
            bB = ffma2(w2[2 * i + 1], v1.y, bB);
        }
        float x0, x1, y0, y1;
        upk2(aA, x0, x1);
        upk2(aB, y0, y1);
        outp[(size_t)r * G] = (x0 + x1) + (y0 + y1);
        upk2(bA, x0, x1);
        upk2(bB, y0, y1);
        outp[(size_t)(r + 1) * G] = (x0 + x1) + (y0 + y1);
    }
}

// ---------------------------------------------------------------------------
// Recurrent scan (round-2 structure: block = 4H threads, R batch rows per
// block, 2 barriers/step, xg prefetch). NEW: per-row accumulator split into
// two chains (accA/accB) halving the serial ffma2 depth.
// ---------------------------------------------------------------------------
template <int H, int R, int MINB>
__global__ void __launch_bounds__(4 * H, MINB) lstm_rec_kernel(
    const float* __restrict__ xg, const float* __restrict__ Whh,
    float* __restrict__ hout)
{
    constexpr int G4 = 4 * H;
    __shared__ __align__(16) float h_sm[R * H];
    __shared__ float g_sm[R * G4];

    const int j = threadIdx.x;
    const int b0 = blockIdx.x * R;
    const int gate = j / H;

    unsigned long long w2[H / 2];
    {
        const unsigned long long* wp = (const unsigned long long*)(Whh + (size_t)j * H);
#pragma unroll
        for (int k = 0; k < H / 2; k++) w2[k] = wp[k];
    }

    for (int i = j; i < R * H; i += G4) h_sm[i] = 0.0f;
    float c = 0.0f;

    const float* xgp = xg + (size_t)b0 * Tn * G4 + j;
    float* hp = hout + (size_t)b0 * Tn * H;

    const int cr = j / H;  // cell-update mapping (first R*H threads)
    const int cm = j % H;

    float xn[R];
#pragma unroll
    for (int r = 0; r < R; r++) xn[r] = xgp[(size_t)r * Tn * G4];

    __syncthreads();

    for (int t = 0; t < Tn; t++) {
        unsigned long long accA[R], accB[R];
#pragma unroll
        for (int r = 0; r < R; r++) {
            accA[r] = pk2(xn[r], 0.0f);
            accB[r] = pk2(0.0f, 0.0f);
        }

        if (t + 1 < Tn) {
#pragma unroll
            for (int r = 0; r < R; r++)
                xn[r] = xgp[((size_t)r * Tn + t + 1) * G4];
        }

#pragma unroll
        for (int k = 0; k < H / 4; k++) {
#pragma unroll
            for (int r = 0; r < R; r++) {
                ulonglong2 hv = ((const ulonglong2*)&h_sm[r * H])[k];
                accA[r] = ffma2(w2[2 * k + 0], hv.x, accA[r]);
                accB[r] = ffma2(w2[2 * k + 1], hv.y, accB[r]);
            }
        }

#pragma unroll
        for (int r = 0; r < R; r++) {
            float l0, h0, l1, h1;
            upk2(accA[r], l0, h0);
            upk2(accB[r], l1, h1);
            float a = (l0 + h0) + (l1 + h1);
            a = (gate == 2) ? ftanh(a) : fsig(a);
            g_sm[r * G4 + j] = a;
        }
        __syncthreads();

        if (j < R * H) {
            const float iv = g_sm[cr * G4 + 0 * H + cm];
            const float fv = g_sm[cr * G4 + 1 * H + cm];
            const float gv = g_sm[cr * G4 + 2 * H + cm];
            const float ov = g_sm[cr * G4 + 3 * H + cm];
            c = fv * c + iv * gv;
            const float h = ov * ftanh(c);
            h_sm[cr * H + cm] = h;
            hp[((size_t)cr * Tn + t) * H + cm] = h;
        }
        __syncthreads();
    }
}

// ---------------------------------------------------------------------------
extern "C" void kernel_launch(void* const* d_in, const int* in_sizes, int n_in,
                              void* d_out, int out_size)
{
    (void)in_sizes; (void)n_in; (void)out_size;

    const float* x    = (const float*)d_in[0];
    const float* e1W  = (const float*)d_in[1];
    const float* e1U  = (const float*)d_in[2];
    const float* e1bi = (const float*)d_in[3];
    const float* e1bh = (const float*)d_in[4];
    const float* e2W  = (const float*)d_in[5];
    const float* e2U  = (const float*)d_in[6];
    const float* e2bi = (const float*)d_in[7];
    const float* e2bh = (const float*)d_in[8];
    const float* d1W  = (const float*)d_in[9];
    const float* d1U  = (const float*)d_in[10];
    const float* d1bi = (const float*)d_in[11];
    const float* d1bh = (const float*)d_in[12];
    const float* d2W  = (const float*)d_in[13];
    const float* d2U  = (const float*)d_in[14];
    const float* d2bi = (const float*)d_in[15];
    const float* d2bh = (const float*)d_in[16];
    float* out = (float*)d_out;

    float *xg = nullptr, *sa = nullptr, *sb = nullptr;
    cudaGetSymbolAddress((void**)&xg, g_xg);
    cudaGetSymbolAddress((void**)&sa, g_seqA);
    cudaGetSymbolAddress((void**)&sb, g_seqB);

    const int gemmGrid = (int)(BTn / 128);  // 2048

    // e1: 72 -> 64
    gemm_xg_kernel<72, 256><<<gemmGrid, 256>>>(x, e1W, e1bi, e1bh, xg);
    lstm_rec_kernel<64, 2, 2><<<Bn / 2, 256>>>(xg, e1U, sa);
    // e2: 64 -> 32
    gemm_xg_kernel<64, 128><<<gemmGrid, 128>>>(sa, e2W, e2bi, e2bh, xg);
    lstm_rec_kernel<32, 1, 4><<<Bn, 128>>>(xg, e2U, sb);
    // d1: 32 -> 64
    gemm_xg_kernel<32, 256><<<gemmGrid, 256>>>(sb, d1W, d1bi, d1bh, xg);
    lstm_rec_kernel<64, 2, 2><<<Bn / 2, 256>>>(xg, d1U, sa);
    // d2: 64 -> 72
    gemm_xg_kernel<64, 288><<<gemmGrid, 288>>>(sa, d2W, d2bi, d2bh, xg);
    lstm_rec_kernel<72, 2, 2><<<Bn / 2, 288>>>(xg, d2U, out);
}